// round 16
// baseline (speedup 1.0000x reference)
#include <cuda_runtime.h>
#include <cuda_fp16.h>
#include <math.h>
#include <stdint.h>

// Problem constants
#define B_    4096
#define D_    2048
#define H_    2048
#define NB_   4
#define BIN_  512
#define BOUT_ 512
#define EPS_  1e-5f

// ---------------------------------------------------------------------------
// Device scratch (allocation-free)
// ---------------------------------------------------------------------------
__device__ __half g_x16[(size_t)B_ * D_];     // x in fp16
__device__ __half g_c16[(size_t)B_ * D_];     // SiLU(conv(LN(x))) in fp16
__device__ __half g_h16[(size_t)B_ * H_];     // h_prev in fp16
// Transposed weights: [tensor 0..7][NB*512*512] fp16, row=n, col=k
__device__ __half g_wt16[8][(size_t)NB_ * 512 * 512];
__device__ __half g_pre16[4ull * B_ * H_];    // pre-activations z,i,f,o (fp16)

// ---------------------------------------------------------------------------
// PTX helpers
// ---------------------------------------------------------------------------
__device__ __forceinline__ uint32_t smem_u32(const void* p) {
    uint32_t a;
    asm("{ .reg .u64 t; cvta.to.shared.u64 t, %1; cvt.u32.u64 %0, t; }"
        : "=r"(a) : "l"(p));
    return a;
}

__device__ __forceinline__ void cp_async16(uint32_t dst, const void* src) {
    asm volatile("cp.async.cg.shared.global [%0], [%1], 16;"
                 :: "r"(dst), "l"(src) : "memory");
}
#define CP_COMMIT() asm volatile("cp.async.commit_group;" ::: "memory")

__device__ __forceinline__ void ldsm4(uint32_t* r, uint32_t addr) {
    asm volatile("ldmatrix.sync.aligned.m8n8.x4.shared.b16 {%0,%1,%2,%3}, [%4];"
                 : "=r"(r[0]), "=r"(r[1]), "=r"(r[2]), "=r"(r[3]) : "r"(addr));
}

__device__ __forceinline__ void mma16816(float* d, const uint32_t* a, const uint32_t* b) {
    asm volatile(
        "mma.sync.aligned.m16n8k16.row.col.f32.f16.f16.f32 "
        "{%0,%1,%2,%3}, {%4,%5,%6,%7}, {%8,%9}, {%0,%1,%2,%3};"
        : "+f"(d[0]), "+f"(d[1]), "+f"(d[2]), "+f"(d[3])
        : "r"(a[0]), "r"(a[1]), "r"(a[2]), "r"(a[3]), "r"(b[0]), "r"(b[1]));
}

// swizzled 16B-chunk offset inside a (rows x 64B) tile
__device__ __forceinline__ uint32_t swz(int row, int c) {
    return (uint32_t)(row * 64 + ((c ^ ((row >> 1) & 3)) << 4));
}

// ---------------------------------------------------------------------------
// Kernel 1 (fused preprocess): one launch, three independent jobs.
//  bid <  4096           : LayerNorm + causal conv3 + SiLU (row = bid), + x cvt
//  4096 <= bid < 5120    : h_prev fp32->fp16 cvt (8 float4 per thread)
//  5120 <= bid < 7168    : weight transpose+cvt, one 64x64 tile per CTA
// ---------------------------------------------------------------------------
__global__ __launch_bounds__(256) void preprocess_kernel(
    const float* __restrict__ x,
    const float* __restrict__ h_prev,
    const float* __restrict__ ln_g,
    const float* __restrict__ ln_b,
    const float* __restrict__ conv_w,
    const float* __restrict__ conv_b,
    const float* __restrict__ W0, const float* __restrict__ W1,
    const float* __restrict__ W2, const float* __restrict__ W3,
    const float* __restrict__ W4, const float* __restrict__ W5,
    const float* __restrict__ W6, const float* __restrict__ W7)
{
    __shared__ float xn[D_];
    __shared__ float red[16];
    __shared__ __half tr[64][72];   // row stride 144B (16B-aligned)

    const int bid = blockIdx.x;
    const int tid = threadIdx.x;

    if (bid < B_) {
        // ---- LayerNorm + conv + SiLU + x cvt (shfl reductions, 2 barriers) ----
        const int row = bid;
        const int lane = tid & 31, wrp = tid >> 5;
        const float* xr = x + (size_t)row * D_;
        size_t base = (size_t)row * D_;

        float v[8];
        float s = 0.f, ss = 0.f;
#pragma unroll
        for (int i = 0; i < 8; ++i) {
            float t = xr[tid + i * 256];
            v[i] = t; s += t; ss += t * t;
        }
#pragma unroll
        for (int i = 0; i < 8; ++i)
            g_x16[base + tid + i * 256] = __float2half(v[i]);

        // warp-level reduce
#pragma unroll
        for (int off = 16; off > 0; off >>= 1) {
            s  += __shfl_xor_sync(0xffffffffu, s, off);
            ss += __shfl_xor_sync(0xffffffffu, ss, off);
        }
        if (lane == 0) { red[wrp] = s; red[8 + wrp] = ss; }
        __syncthreads();
        float S = 0.f, SS = 0.f;
#pragma unroll
        for (int w = 0; w < 8; ++w) { S += red[w]; SS += red[8 + w]; }

        const float mean = S * (1.0f / D_);
        const float var = SS * (1.0f / D_) - mean * mean;
        const float rstd = rsqrtf(var + EPS_);

#pragma unroll
        for (int i = 0; i < 8; ++i) {
            int d = tid + i * 256;
            xn[d] = (v[i] - mean) * rstd * ln_g[d] + ln_b[d];
        }
        __syncthreads();

        const float w0 = conv_w[0], w1 = conv_w[1], w2 = conv_w[2], cb = conv_b[0];
#pragma unroll
        for (int i = 0; i < 8; ++i) {
            int d = tid + i * 256;
            float a0 = (d >= 2) ? xn[d - 2] : 0.f;
            float a1 = (d >= 1) ? xn[d - 1] : 0.f;
            float xc = w0 * a0 + w1 * a1 + w2 * xn[d] + cb;
            float sg = 1.f / (1.f + expf(-xc));
            g_c16[base + d] = __float2half(xc * sg);
        }
    } else if (bid < B_ + 1024) {
        // ---- h_prev cvt: 1024 CTAs x 256 threads x 8 float4 = B*H/4 ----
        const int cb2 = bid - B_;
        __half* h16 = g_h16;
#pragma unroll
        for (int k = 0; k < 8; ++k) {
            size_t i = (size_t)cb2 * 2048 + k * 256 + tid;
            float4 v = ((const float4*)h_prev)[i];
            __half h[4] = { __float2half(v.x), __float2half(v.y),
                            __float2half(v.z), __float2half(v.w) };
            ((uint2*)h16)[i] = *(uint2*)h;
        }
    } else {
        // ---- weight transpose: tile t in 0..2047 ----
        const int t = bid - (B_ + 1024);
        const int n0 = (t & 7) * 64;
        const int k0 = ((t >> 3) & 7) * 64;
        const int z = t >> 6;             // 0..31 = tens*4 + nb
        const int tens = z >> 2, nb = z & 3;
        const float* Ws[8] = {W0, W1, W2, W3, W4, W5, W6, W7};
        const float* Wb = Ws[tens] + (size_t)nb * 512 * 512;
        __half* Th = g_wt16[tens] + (size_t)nb * 512 * 512;

#pragma unroll
        for (int it = 0; it < 4; ++it) {
            int q = tid + it * 256;
            int k = q >> 4, nq = (q & 15) * 4;
            float4 v = *(const float4*)(Wb + (size_t)(k0 + k) * 512 + n0 + nq);
            tr[nq + 0][k] = __float2half(v.x);
            tr[nq + 1][k] = __float2half(v.y);
            tr[nq + 2][k] = __float2half(v.z);
            tr[nq + 3][k] = __float2half(v.w);
        }
        __syncthreads();
#pragma unroll
        for (int it = 0; it < 2; ++it) {
            int sidx = tid + it * 256;
            int n = sidx >> 3, ch = (sidx & 7) * 8;
            uint4 val = *(const uint4*)&tr[n][ch];
            *(uint4*)(Th + (size_t)(n0 + n) * 512 + k0 + ch) = val;
        }
    }
}

// ---------------------------------------------------------------------------
// Kernel 2: persistent mma.sync fp16 GEMM.  Tile M=128 N=128 K=1024.
// 2048 logical tiles (tile id t: ntile=t&3, mtile=(t>>2)&31, z=t>>7).
// grid 304 persistent CTAs x 256 threads (8 warps, 32x64), 2 CTAs/SM.
// Continuous 4-buffer cp.async pipeline ACROSS tiles (producer 3 chunks ahead).
// Epilogue: fp16 (half2) stores to g_pre16.
// ---------------------------------------------------------------------------
#define STAGE_BYTES 16384
#define OFF_A 0
#define OFF_B 8192
#define SMEM_TOTAL_G (4 * STAGE_BYTES)
#define NTILES 2048
#define GRID_P 304

__global__ __launch_bounds__(256, 2) void gemm_mma_kernel()
{
    extern __shared__ __align__(128) char smem[];
    const uint32_t sbase = smem_u32(smem);
    const int tid = threadIdx.x;
    const int lane = tid & 31;
    const int wid = tid >> 5;
    const int wm = wid & 3;          // warp row (4) -> 32 rows each
    const int wn = wid >> 2;         // warp col (2) -> 64 cols each
    const int g = lane >> 3, lr = lane & 7;

    // ---- producer: load chunk c of tile t into buffer buf ----
    auto load_chunk = [&](int t, int c, int buf) {
        const int ntile = t & 3, mtile = (t >> 2) & 31;
        const int z = t >> 7;
        const int gate = z >> 2, nblk = z & 3;
        const __half *A, *Bw;
        int kc;
        if (c < 16) {
            A = (gate == 0 || gate == 3) ? g_x16 : g_c16;
            Bw = g_wt16[gate]; kc = c * 32;
        } else {
            A = g_h16; Bw = g_wt16[4 + gate]; kc = (c - 16) * 32;
        }
        const size_t aoff = (size_t)(mtile * 128) * D_ + nblk * 512 + kc;
        const size_t boff = (size_t)nblk * (512 * 512) + (size_t)(ntile * 128) * 512 + kc;
        const uint32_t sb = sbase + (uint32_t)buf * STAGE_BYTES;
#pragma unroll
        for (int i = 0; i < 2; ++i) {
            int q = tid + i * 256;
            int row = q >> 2, cc = q & 3;
            cp_async16(sb + OFF_A + swz(row, cc), A + aoff + (size_t)row * D_ + cc * 8);
        }
#pragma unroll
        for (int i = 0; i < 2; ++i) {
            int q = tid + i * 256;
            int row = q >> 2, cc = q & 3;
            cp_async16(sb + OFF_B + swz(row, cc), Bw + boff + (size_t)row * 512 + cc * 8);
        }
    };

    // producer cursor
    int pt = blockIdx.x;   // tile being loaded
    int pc = 0;            // chunk within tile
    int pbuf = 0;
    int lead = 0;          // chunks loaded but not yet consumed

    while (lead < 3 && pt < NTILES) {
        load_chunk(pt, pc, pbuf); CP_COMMIT();
        pbuf = (pbuf + 1) & 3; ++lead;
        if (++pc == 32) { pc = 0; pt += GRID_P; }
    }

    int cbuf = 0;
#pragma unroll 1
    for (int t = blockIdx.x; t < NTILES; t += GRID_P) {
        float acc[2][8][4];
#pragma unroll
        for (int i = 0; i < 2; ++i)
#pragma unroll
            for (int j = 0; j < 8; ++j)
#pragma unroll
                for (int k = 0; k < 4; ++k) acc[i][j][k] = 0.f;

#pragma unroll 1
        for (int c = 0; c < 32; ++c) {
            if (lead >= 3)      asm volatile("cp.async.wait_group 2;" ::: "memory");
            else if (lead == 2) asm volatile("cp.async.wait_group 1;" ::: "memory");
            else                asm volatile("cp.async.wait_group 0;" ::: "memory");
            __syncthreads();
            if (pt < NTILES) {
                load_chunk(pt, pc, pbuf); CP_COMMIT();
                pbuf = (pbuf + 1) & 3;
                if (++pc == 32) { pc = 0; pt += GRID_P; }
            } else {
                --lead;
            }

            const uint32_t sb = sbase + (uint32_t)cbuf * STAGE_BYTES;
#pragma unroll
            for (int ks = 0; ks < 2; ++ks) {
                uint32_t bf[4][4];
#pragma unroll
                for (int nq = 0; nq < 4; ++nq) {
                    int nrow = wn * 64 + nq * 16 + (g >> 1) * 8 + lr;
                    ldsm4(bf[nq], sb + OFF_B + swz(nrow, ks * 2 + (g & 1)));
                }
#pragma unroll
                for (int mh = 0; mh < 2; ++mh) {
                    uint32_t af[4];
                    int row = wm * 32 + mh * 16 + (g & 1) * 8 + lr;
                    ldsm4(af, sb + OFF_A + swz(row, ks * 2 + (g >> 1)));
#pragma unroll
                    for (int nq = 0; nq < 4; ++nq)
#pragma unroll
                        for (int sub = 0; sub < 2; ++sub)
                            mma16816(acc[mh][nq * 2 + sub], af, &bf[nq][sub * 2]);
                }
            }
            cbuf = (cbuf + 1) & 3;
        }

        // Epilogue for tile t (next tile's loads already in flight)
        const int ntile = t & 3, mtile = (t >> 2) & 31;
        const int z = t >> 7;
        const int gate = z >> 2, nblk = z & 3;
        __half* outp = g_pre16 + (size_t)gate * B_ * H_;
        const int colb = nblk * 512 + ntile * 128 + wn * 64 + (lane & 3) * 2;
        const int rowb = mtile * 128 + wm * 32 + (lane >> 2);
#pragma unroll
        for (int mh = 0; mh < 2; ++mh)
#pragma unroll
            for (int n8 = 0; n8 < 8; ++n8) {
                int col = colb + n8 * 8;
                int r0 = rowb + mh * 16;
                __half* p0 = outp + (size_t)r0 * H_ + col;
                __half* p1 = outp + (size_t)(r0 + 8) * H_ + col;
                *(__half2*)p0 = __floats2half2_rn(acc[mh][n8][0], acc[mh][n8][1]);
                *(__half2*)p1 = __floats2half2_rn(acc[mh][n8][2], acc[mh][n8][3]);
            }
    }
}

// ---------------------------------------------------------------------------
// Kernel 3: gates + state update.  4 elems/thread; fp16 pre loads.
// ---------------------------------------------------------------------------
__global__ __launch_bounds__(256) void gates_kernel(
    const float* __restrict__ c_prev,
    const float* __restrict__ bz, const float* __restrict__ bi,
    const float* __restrict__ bf, const float* __restrict__ bo,
    const float* __restrict__ rbz, const float* __restrict__ rbi,
    const float* __restrict__ rbf, const float* __restrict__ rbo,
    float* __restrict__ out_h, float* __restrict__ out_c)
{
    const size_t n4 = (size_t)B_ * H_ / 4;
    size_t i = (size_t)blockIdx.x * blockDim.x + threadIdx.x;
    if (i >= n4) return;
    const size_t n = (size_t)B_ * H_;
    int j4 = (int)((i * 4) & (H_ - 1));

    uint2 uz = ((const uint2*)(g_pre16 + 0 * n))[i];
    uint2 ui = ((const uint2*)(g_pre16 + 1 * n))[i];
    uint2 uf = ((const uint2*)(g_pre16 + 2 * n))[i];
    uint2 uo = ((const uint2*)(g_pre16 + 3 * n))[i];
    float2 za = __half22float2(*(__half2*)&uz.x), zb = __half22float2(*(__half2*)&uz.y);
    float2 ia = __half22float2(*(__half2*)&ui.x), ib = __half22float2(*(__half2*)&ui.y);
    float2 fa = __half22float2(*(__half2*)&uf.x), fb = __half22float2(*(__half2*)&uf.y);
    float2 oa = __half22float2(*(__half2*)&uo.x), ob = __half22float2(*(__half2*)&uo.y);

    float4 cp4 = ((const float4*)c_prev)[i];
    float4 bz4 = *(const float4*)(bz + j4), rz4 = *(const float4*)(rbz + j4);
    float4 bi4 = *(const float4*)(bi + j4), ri4 = *(const float4*)(rbi + j4);
    float4 bf4 = *(const float4*)(bf + j4), rf4 = *(const float4*)(rbf + j4);
    float4 bo4 = *(const float4*)(bo + j4), ro4 = *(const float4*)(rbo + j4);

    float h[4], cc[4];
    float pzv[4] = {za.x + bz4.x + rz4.x, za.y + bz4.y + rz4.y,
                    zb.x + bz4.z + rz4.z, zb.y + bz4.w + rz4.w};
    float piv[4] = {ia.x + bi4.x + ri4.x, ia.y + bi4.y + ri4.y,
                    ib.x + bi4.z + ri4.z, ib.y + bi4.w + ri4.w};
    float pfv[4] = {fa.x + bf4.x + rf4.x, fa.y + bf4.y + rf4.y,
                    fb.x + bf4.z + rf4.z, fb.y + bf4.w + rf4.w};
    float pov[4] = {oa.x + bo4.x + ro4.x, oa.y + bo4.y + ro4.y,
                    ob.x + bo4.z + ro4.z, ob.y + bo4.w + ro4.w};
    float cpv[4] = {cp4.x, cp4.y, cp4.z, cp4.w};
#pragma unroll
    for (int k = 0; k < 4; ++k) {
        float z  = tanhf(pzv[k]);
        float ig = 1.f / (1.f + expf(-piv[k]));
        float fg = 1.f / (1.f + expf(-pfv[k]));
        float og = 1.f / (1.f + expf(-pov[k]));
        cc[k] = fg * cpv[k] + ig * z;
        h[k]  = og * tanhf(cc[k]);
    }
    ((float4*)out_h)[i] = make_float4(h[0], h[1], h[2], h[3]);
    ((float4*)out_c)[i] = make_float4(cc[0], cc[1], cc[2], cc[3]);
}

// ---------------------------------------------------------------------------
// Launch
// ---------------------------------------------------------------------------
extern "C" void kernel_launch(void* const* d_in, const int* in_sizes, int n_in,
                              void* d_out, int out_size)
{
    const float* x      = (const float*)d_in[0];
    const float* h_prev = (const float*)d_in[1];
    const float* c_prev = (const float*)d_in[2];
    const float* ln_g   = (const float*)d_in[3];
    const float* ln_b   = (const float*)d_in[4];
    const float* conv_w = (const float*)d_in[5];
    const float* conv_b = (const float*)d_in[6];
    const float* Wz = (const float*)d_in[7],  *bz  = (const float*)d_in[8];
    const float* Wi = (const float*)d_in[9],  *bi  = (const float*)d_in[10];
    const float* Wf = (const float*)d_in[11], *bf  = (const float*)d_in[12];
    const float* Wo = (const float*)d_in[13], *bo  = (const float*)d_in[14];
    const float* Rz = (const float*)d_in[15], *rbz = (const float*)d_in[16];
    const float* Ri = (const float*)d_in[17], *rbi = (const float*)d_in[18];
    const float* Rf = (const float*)d_in[19], *rbf = (const float*)d_in[20];
    const float* Ro = (const float*)d_in[21], *rbo = (const float*)d_in[22];

    float* out = (float*)d_out;

    cudaFuncSetAttribute(gemm_mma_kernel,
                         cudaFuncAttributeMaxDynamicSharedMemorySize, SMEM_TOTAL_G);

    const size_t nelem = (size_t)B_ * H_;

    // launch 1: fused preprocess (LN+conv+SiLU+x cvt | h cvt | weight transpose)
    preprocess_kernel<<<B_ + 1024 + 2048, 256>>>(
        x, h_prev, ln_g, ln_b, conv_w, conv_b,
        Wz, Wi, Wf, Wo, Rz, Ri, Rf, Ro);

    // launch 2: persistent GEMM over all 2048 tiles
    gemm_mma_kernel<<<GRID_P, 256, SMEM_TOTAL_G>>>();

    // launch 3: gates + state update
    gates_kernel<<<(int)((nelem / 4 + 255) / 256), 256>>>(
        c_prev, bz, bi, bf, bo, rbz, rbi, rbf, rbo, out, out + nelem);
}

// round 17
// speedup vs baseline: 1.0550x; 1.0550x over previous
#include <cuda_runtime.h>
#include <cuda_fp16.h>
#include <math.h>
#include <stdint.h>

// Problem constants
#define B_    4096
#define D_    2048
#define H_    2048
#define NB_   4
#define BIN_  512
#define BOUT_ 512
#define EPS_  1e-5f

// ---------------------------------------------------------------------------
// Device scratch (allocation-free)
// ---------------------------------------------------------------------------
__device__ __half g_x16[(size_t)B_ * D_];     // x in fp16
__device__ __half g_c16[(size_t)B_ * D_];     // SiLU(conv(LN(x))) in fp16
__device__ __half g_h16[(size_t)B_ * H_];     // h_prev in fp16
// Transposed weights: [tensor 0..7][NB*512*512] fp16, row=n, col=k
__device__ __half g_wt16[8][(size_t)NB_ * 512 * 512];
__device__ __half g_pre16[4ull * B_ * H_];    // pre-activations z,i,f,o (fp16)

// ---------------------------------------------------------------------------
// PTX helpers
// ---------------------------------------------------------------------------
__device__ __forceinline__ uint32_t smem_u32(const void* p) {
    uint32_t a;
    asm("{ .reg .u64 t; cvta.to.shared.u64 t, %1; cvt.u32.u64 %0, t; }"
        : "=r"(a) : "l"(p));
    return a;
}

__device__ __forceinline__ void cp_async16(uint32_t dst, const void* src) {
    asm volatile("cp.async.cg.shared.global [%0], [%1], 16;"
                 :: "r"(dst), "l"(src) : "memory");
}
#define CP_COMMIT() asm volatile("cp.async.commit_group;" ::: "memory")

__device__ __forceinline__ void ldsm4(uint32_t* r, uint32_t addr) {
    asm volatile("ldmatrix.sync.aligned.m8n8.x4.shared.b16 {%0,%1,%2,%3}, [%4];"
                 : "=r"(r[0]), "=r"(r[1]), "=r"(r[2]), "=r"(r[3]) : "r"(addr));
}

__device__ __forceinline__ void mma16816(float* d, const uint32_t* a, const uint32_t* b) {
    asm volatile(
        "mma.sync.aligned.m16n8k16.row.col.f32.f16.f16.f32 "
        "{%0,%1,%2,%3}, {%4,%5,%6,%7}, {%8,%9}, {%0,%1,%2,%3};"
        : "+f"(d[0]), "+f"(d[1]), "+f"(d[2]), "+f"(d[3])
        : "r"(a[0]), "r"(a[1]), "r"(a[2]), "r"(a[3]), "r"(b[0]), "r"(b[1]));
}

// swizzled 16B-chunk offset inside a (rows x 64B) tile
__device__ __forceinline__ uint32_t swz(int row, int c) {
    return (uint32_t)(row * 64 + ((c ^ ((row >> 1) & 3)) << 4));
}

// ---------------------------------------------------------------------------
// Kernel 1 (fused preprocess): one launch, three independent jobs.
//  bid <  4096           : LayerNorm + causal conv3 + SiLU (row = bid), + x cvt
//  4096 <= bid < 5120    : h_prev fp32->fp16 cvt (8 float4 per thread)
//  5120 <= bid < 7168    : weight transpose+cvt, one 64x64 tile per CTA
// ---------------------------------------------------------------------------
__global__ __launch_bounds__(256) void preprocess_kernel(
    const float* __restrict__ x,
    const float* __restrict__ h_prev,
    const float* __restrict__ ln_g,
    const float* __restrict__ ln_b,
    const float* __restrict__ conv_w,
    const float* __restrict__ conv_b,
    const float* __restrict__ W0, const float* __restrict__ W1,
    const float* __restrict__ W2, const float* __restrict__ W3,
    const float* __restrict__ W4, const float* __restrict__ W5,
    const float* __restrict__ W6, const float* __restrict__ W7)
{
    __shared__ float xn[D_];
    __shared__ float red[16];
    __shared__ __half tr[64][72];   // row stride 144B (16B-aligned)

    const int bid = blockIdx.x;
    const int tid = threadIdx.x;

    if (bid < B_) {
        // ---- LayerNorm + conv + SiLU + x cvt (shfl reductions, 2 barriers) ----
        const int row = bid;
        const int lane = tid & 31, wrp = tid >> 5;
        const float* xr = x + (size_t)row * D_;
        size_t base = (size_t)row * D_;

        float v[8];
        float s = 0.f, ss = 0.f;
#pragma unroll
        for (int i = 0; i < 8; ++i) {
            float t = xr[tid + i * 256];
            v[i] = t; s += t; ss += t * t;
        }
#pragma unroll
        for (int i = 0; i < 8; ++i)
            g_x16[base + tid + i * 256] = __float2half(v[i]);

        // warp-level reduce
#pragma unroll
        for (int off = 16; off > 0; off >>= 1) {
            s  += __shfl_xor_sync(0xffffffffu, s, off);
            ss += __shfl_xor_sync(0xffffffffu, ss, off);
        }
        if (lane == 0) { red[wrp] = s; red[8 + wrp] = ss; }
        __syncthreads();
        float S = 0.f, SS = 0.f;
#pragma unroll
        for (int w = 0; w < 8; ++w) { S += red[w]; SS += red[8 + w]; }

        const float mean = S * (1.0f / D_);
        const float var = SS * (1.0f / D_) - mean * mean;
        const float rstd = rsqrtf(var + EPS_);

#pragma unroll
        for (int i = 0; i < 8; ++i) {
            int d = tid + i * 256;
            xn[d] = (v[i] - mean) * rstd * ln_g[d] + ln_b[d];
        }
        __syncthreads();

        const float w0 = conv_w[0], w1 = conv_w[1], w2 = conv_w[2], cb = conv_b[0];
#pragma unroll
        for (int i = 0; i < 8; ++i) {
            int d = tid + i * 256;
            float a0 = (d >= 2) ? xn[d - 2] : 0.f;
            float a1 = (d >= 1) ? xn[d - 1] : 0.f;
            float xc = w0 * a0 + w1 * a1 + w2 * xn[d] + cb;
            float sg = 1.f / (1.f + expf(-xc));
            g_c16[base + d] = __float2half(xc * sg);
        }
    } else if (bid < B_ + 1024) {
        // ---- h_prev cvt: 1024 CTAs x 256 threads x 8 float4 = B*H/4 ----
        const int cb2 = bid - B_;
        __half* h16 = g_h16;
#pragma unroll
        for (int k = 0; k < 8; ++k) {
            size_t i = (size_t)cb2 * 2048 + k * 256 + tid;
            float4 v = ((const float4*)h_prev)[i];
            __half h[4] = { __float2half(v.x), __float2half(v.y),
                            __float2half(v.z), __float2half(v.w) };
            ((uint2*)h16)[i] = *(uint2*)h;
        }
    } else {
        // ---- weight transpose: tile t in 0..2047 ----
        const int t = bid - (B_ + 1024);
        const int n0 = (t & 7) * 64;
        const int k0 = ((t >> 3) & 7) * 64;
        const int z = t >> 6;             // 0..31 = tens*4 + nb
        const int tens = z >> 2, nb = z & 3;
        const float* Ws[8] = {W0, W1, W2, W3, W4, W5, W6, W7};
        const float* Wb = Ws[tens] + (size_t)nb * 512 * 512;
        __half* Th = g_wt16[tens] + (size_t)nb * 512 * 512;

#pragma unroll
        for (int it = 0; it < 4; ++it) {
            int q = tid + it * 256;
            int k = q >> 4, nq = (q & 15) * 4;
            float4 v = *(const float4*)(Wb + (size_t)(k0 + k) * 512 + n0 + nq);
            tr[nq + 0][k] = __float2half(v.x);
            tr[nq + 1][k] = __float2half(v.y);
            tr[nq + 2][k] = __float2half(v.z);
            tr[nq + 3][k] = __float2half(v.w);
        }
        __syncthreads();
#pragma unroll
        for (int it = 0; it < 2; ++it) {
            int sidx = tid + it * 256;
            int n = sidx >> 3, ch = (sidx & 7) * 8;
            uint4 val = *(const uint4*)&tr[n][ch];
            *(uint4*)(Th + (size_t)(n0 + n) * 512 + k0 + ch) = val;
        }
    }
}

// ---------------------------------------------------------------------------
// Kernel 2: mma.sync fp16 GEMM.  CTA tile M=128 N=128 K=1024 (W then R).
// grid: (4 ntile, 32 mtile, 16 = gate*4+nblk), 256 threads (8 warps, 32x64).
// 2 CTAs/SM (regs capped at 128). smem: 4 stages x (A 8K + B 8K) = 64KB.
// Epilogue: fp16 (half2) stores to g_pre16.
// ---------------------------------------------------------------------------
#define STAGE_BYTES 16384
#define OFF_A 0
#define OFF_B 8192
#define SMEM_TOTAL_G (4 * STAGE_BYTES)

__global__ __launch_bounds__(256, 2) void gemm_mma_kernel()
{
    extern __shared__ __align__(128) char smem[];
    const uint32_t sbase = smem_u32(smem);
    const int tid = threadIdx.x;
    const int lane = tid & 31;
    const int wid = tid >> 5;
    const int wm = wid & 3;          // warp row (4) -> 32 rows each
    const int wn = wid >> 2;         // warp col (2) -> 64 cols each

    const int ntile = blockIdx.x, mtile = blockIdx.y;
    const int gate = blockIdx.z >> 2, nblk = blockIdx.z & 3;
    const int row0 = mtile * 128;
    const int n0 = ntile * 128;

    const __half* a16 = (gate == 0 || gate == 3) ? g_x16 : g_c16;
    const __half* bw = g_wt16[gate];
    const __half* br = g_wt16[4 + gate];

    float acc[2][8][4];   // mh (16-row), n8 (8-col), frag
#pragma unroll
    for (int i = 0; i < 2; ++i)
#pragma unroll
        for (int j = 0; j < 8; ++j)
#pragma unroll
            for (int k = 0; k < 4; ++k) acc[i][j][k] = 0.f;

    // ---- load one k-chunk (32 k) into stage buf ----
    auto load_chunk = [&](int c, int buf) {
        const __half *A, *Bw;
        int kc;
        if (c < 16) { A = a16;   Bw = bw; kc = c * 32; }
        else        { A = g_h16; Bw = br; kc = (c - 16) * 32; }
        const size_t aoff = (size_t)row0 * D_ + nblk * 512 + kc;
        const size_t boff = (size_t)nblk * (512 * 512) + (size_t)n0 * 512 + kc;
        const uint32_t sb = sbase + (uint32_t)buf * STAGE_BYTES;
        // A: 128 rows x 4 16B-chunks = 512; 2 per thread
#pragma unroll
        for (int i = 0; i < 2; ++i) {
            int q = tid + i * 256;
            int row = q >> 2, cc = q & 3;
            cp_async16(sb + OFF_A + swz(row, cc), A + aoff + (size_t)row * D_ + cc * 8);
        }
        // B: 128 rows x 4 chunks = 512; 2 per thread
#pragma unroll
        for (int i = 0; i < 2; ++i) {
            int q = tid + i * 256;
            int row = q >> 2, cc = q & 3;
            cp_async16(sb + OFF_B + swz(row, cc), Bw + boff + (size_t)row * 512 + cc * 8);
        }
    };

    const int g = lane >> 3, lr = lane & 7;

    load_chunk(0, 0); CP_COMMIT();
    load_chunk(1, 1); CP_COMMIT();
    load_chunk(2, 2); CP_COMMIT();

#pragma unroll 1
    for (int c = 0; c < 32; ++c) {
        if (c <= 29)      asm volatile("cp.async.wait_group 2;" ::: "memory");
        else if (c == 30) asm volatile("cp.async.wait_group 1;" ::: "memory");
        else              asm volatile("cp.async.wait_group 0;" ::: "memory");
        __syncthreads();
        if (c + 3 < 32) { load_chunk(c + 3, (c + 3) & 3); CP_COMMIT(); }

        const uint32_t sb = sbase + (uint32_t)(c & 3) * STAGE_BYTES;

#pragma unroll
        for (int ks = 0; ks < 2; ++ks) {
            uint32_t bf[4][4];
#pragma unroll
            for (int nq = 0; nq < 4; ++nq) {
                int nrow = wn * 64 + nq * 16 + (g >> 1) * 8 + lr;
                ldsm4(bf[nq], sb + OFF_B + swz(nrow, ks * 2 + (g & 1)));
            }
#pragma unroll
            for (int mh = 0; mh < 2; ++mh) {
                uint32_t af[4];
                int row = wm * 32 + mh * 16 + (g & 1) * 8 + lr;
                ldsm4(af, sb + OFF_A + swz(row, ks * 2 + (g >> 1)));
#pragma unroll
                for (int nq = 0; nq < 4; ++nq)
#pragma unroll
                    for (int sub = 0; sub < 2; ++sub)
                        mma16816(acc[mh][nq * 2 + sub], af, &bf[nq][sub * 2]);
            }
        }
    }

    // Epilogue: fp16 (half2) stores to g_pre16
    __half* outp = g_pre16 + (size_t)gate * B_ * H_;
    const int colb = nblk * 512 + n0 + wn * 64 + (lane & 3) * 2;
    const int rowb = row0 + wm * 32 + (lane >> 2);
#pragma unroll
    for (int mh = 0; mh < 2; ++mh)
#pragma unroll
        for (int n8 = 0; n8 < 8; ++n8) {
            int col = colb + n8 * 8;
            int r0 = rowb + mh * 16;
            __half* p0 = outp + (size_t)r0 * H_ + col;
            __half* p1 = outp + (size_t)(r0 + 8) * H_ + col;
            *(__half2*)p0 = __floats2half2_rn(acc[mh][n8][0], acc[mh][n8][1]);
            *(__half2*)p1 = __floats2half2_rn(acc[mh][n8][2], acc[mh][n8][3]);
        }
}

// ---------------------------------------------------------------------------
// Kernel 3: gates + state update.  4 elems/thread; fp16 pre loads.
// ---------------------------------------------------------------------------
__global__ __launch_bounds__(256) void gates_kernel(
    const float* __restrict__ c_prev,
    const float* __restrict__ bz, const float* __restrict__ bi,
    const float* __restrict__ bf, const float* __restrict__ bo,
    const float* __restrict__ rbz, const float* __restrict__ rbi,
    const float* __restrict__ rbf, const float* __restrict__ rbo,
    float* __restrict__ out_h, float* __restrict__ out_c)
{
    const size_t n4 = (size_t)B_ * H_ / 4;
    size_t i = (size_t)blockIdx.x * blockDim.x + threadIdx.x;
    if (i >= n4) return;
    const size_t n = (size_t)B_ * H_;
    int j4 = (int)((i * 4) & (H_ - 1));

    uint2 uz = ((const uint2*)(g_pre16 + 0 * n))[i];
    uint2 ui = ((const uint2*)(g_pre16 + 1 * n))[i];
    uint2 uf = ((const uint2*)(g_pre16 + 2 * n))[i];
    uint2 uo = ((const uint2*)(g_pre16 + 3 * n))[i];
    float2 za = __half22float2(*(__half2*)&uz.x), zb = __half22float2(*(__half2*)&uz.y);
    float2 ia = __half22float2(*(__half2*)&ui.x), ib = __half22float2(*(__half2*)&ui.y);
    float2 fa = __half22float2(*(__half2*)&uf.x), fb = __half22float2(*(__half2*)&uf.y);
    float2 oa = __half22float2(*(__half2*)&uo.x), ob = __half22float2(*(__half2*)&uo.y);

    float4 cp4 = ((const float4*)c_prev)[i];
    float4 bz4 = *(const float4*)(bz + j4), rz4 = *(const float4*)(rbz + j4);
    float4 bi4 = *(const float4*)(bi + j4), ri4 = *(const float4*)(rbi + j4);
    float4 bf4 = *(const float4*)(bf + j4), rf4 = *(const float4*)(rbf + j4);
    float4 bo4 = *(const float4*)(bo + j4), ro4 = *(const float4*)(rbo + j4);

    float h[4], cc[4];
    float pzv[4] = {za.x + bz4.x + rz4.x, za.y + bz4.y + rz4.y,
                    zb.x + bz4.z + rz4.z, zb.y + bz4.w + rz4.w};
    float piv[4] = {ia.x + bi4.x + ri4.x, ia.y + bi4.y + ri4.y,
                    ib.x + bi4.z + ri4.z, ib.y + bi4.w + ri4.w};
    float pfv[4] = {fa.x + bf4.x + rf4.x, fa.y + bf4.y + rf4.y,
                    fb.x + bf4.z + rf4.z, fb.y + bf4.w + rf4.w};
    float pov[4] = {oa.x + bo4.x + ro4.x, oa.y + bo4.y + ro4.y,
                    ob.x + bo4.z + ro4.z, ob.y + bo4.w + ro4.w};
    float cpv[4] = {cp4.x, cp4.y, cp4.z, cp4.w};
#pragma unroll
    for (int k = 0; k < 4; ++k) {
        float z  = tanhf(pzv[k]);
        float ig = 1.f / (1.f + expf(-piv[k]));
        float fg = 1.f / (1.f + expf(-pfv[k]));
        float og = 1.f / (1.f + expf(-pov[k]));
        cc[k] = fg * cpv[k] + ig * z;
        h[k]  = og * tanhf(cc[k]);
    }
    ((float4*)out_h)[i] = make_float4(h[0], h[1], h[2], h[3]);
    ((float4*)out_c)[i] = make_float4(cc[0], cc[1], cc[2], cc[3]);
}

// ---------------------------------------------------------------------------
// Launch
// ---------------------------------------------------------------------------
extern "C" void kernel_launch(void* const* d_in, const int* in_sizes, int n_in,
                              void* d_out, int out_size)
{
    const float* x      = (const float*)d_in[0];
    const float* h_prev = (const float*)d_in[1];
    const float* c_prev = (const float*)d_in[2];
    const float* ln_g   = (const float*)d_in[3];
    const float* ln_b   = (const float*)d_in[4];
    const float* conv_w = (const float*)d_in[5];
    const float* conv_b = (const float*)d_in[6];
    const float* Wz = (const float*)d_in[7],  *bz  = (const float*)d_in[8];
    const float* Wi = (const float*)d_in[9],  *bi  = (const float*)d_in[10];
    const float* Wf = (const float*)d_in[11], *bf  = (const float*)d_in[12];
    const float* Wo = (const float*)d_in[13], *bo  = (const float*)d_in[14];
    const float* Rz = (const float*)d_in[15], *rbz = (const float*)d_in[16];
    const float* Ri = (const float*)d_in[17], *rbi = (const float*)d_in[18];
    const float* Rf = (const float*)d_in[19], *rbf = (const float*)d_in[20];
    const float* Ro = (const float*)d_in[21], *rbo = (const float*)d_in[22];

    float* out = (float*)d_out;

    cudaFuncSetAttribute(gemm_mma_kernel,
                         cudaFuncAttributeMaxDynamicSharedMemorySize, SMEM_TOTAL_G);

    const size_t nelem = (size_t)B_ * H_;

    // launch 1: fused preprocess (LN+conv+SiLU+x cvt | h cvt | weight transpose)
    preprocess_kernel<<<B_ + 1024 + 2048, 256>>>(
        x, h_prev, ln_g, ln_b, conv_w, conv_b,
        Wz, Wi, Wf, Wo, Rz, Ri, Rf, Ro);

    // launch 2: all GEMMs
    dim3 ggrid(4, 32, 16);
    gemm_mma_kernel<<<ggrid, 256, SMEM_TOTAL_G>>>();

    // launch 3: gates + state update
    gates_kernel<<<(int)((nelem / 4 + 255) / 256), 256>>>(
        c_prev, bz, bi, bf, bo, rbz, rbi, rbf, rbo, out, out + nelem);
}